// round 1
// baseline (speedup 1.0000x reference)
#include <cuda_runtime.h>
#include <cuda_fp16.h>
#include <mma.h>

using namespace nvcuda;

// Fixed problem maxima (B=4, S=2048, IN=4096, OUT=4096)
#define IN_MAX  4096
#define OUT_MAX 4096
#define M_MAX   8192

// Scratch (static device globals — allocation-free per harness rules)
__device__ __half g_W[(size_t)IN_MAX * OUT_MAX];   // dequantized weights, row-major [K][N]
__device__ __half g_X[(size_t)M_MAX * IN_MAX];     // fp16 copy of x, row-major [M][K]

// ---------------------------------------------------------------------------
// Kernel A: x fp32 -> fp16
// ---------------------------------------------------------------------------
__global__ void convert_x_kernel(const float* __restrict__ x, int n4) {
    int i = blockIdx.x * blockDim.x + threadIdx.x;
    if (i < n4) {
        float4 v = reinterpret_cast<const float4*>(x)[i];
        __half2 a = __floats2half2_rn(v.x, v.y);
        __half2 b = __floats2half2_rn(v.z, v.w);
        __half2* o = reinterpret_cast<__half2*>(g_X) + 2 * (size_t)i;
        o[0] = a;
        o[1] = b;
    }
}

// ---------------------------------------------------------------------------
// Kernel B: dequantize 4-bit weights -> fp16 [K][N]
// One thread per packed qweight word (covers 8 input rows, one output col).
// ---------------------------------------------------------------------------
__global__ void dequant_kernel(const int* __restrict__ qweight,
                               const int* __restrict__ qzeros,
                               const int* __restrict__ qscales,
                               const float* __restrict__ qscales_zeros,
                               const float* __restrict__ qscales_scales,
                               const int* __restrict__ g_idx,
                               int INF, int OUT) {
    int idx = blockIdx.x * blockDim.x + threadIdx.x;     // p * OUT + j
    int P = INF >> 3;
    if (idx >= P * OUT) return;
    int p = idx / OUT;
    int j = idx - p * OUT;

    unsigned int wword = (unsigned int)qweight[idx];
    int zcol   = j >> 3;
    int zshift = (j & 7) * 4;
    int outd8  = OUT >> 3;

    int   g_prev = -1;
    float sc     = 0.f;
    int   z      = 0;

#pragma unroll
    for (int r = 0; r < 8; r++) {
        int row = p * 8 + r;
        int g = g_idx[row];
        if (g != g_prev) {
            g_prev = g;
            z  = (int)(((unsigned int)qzeros[g * outd8 + zcol] >> zshift) & 15u) + 1;
            sc = ((float)qscales[(size_t)g * OUT + j] - qscales_zeros[g]) * qscales_scales[g];
        }
        int wn = (int)((wword >> (4 * r)) & 15u);
        g_W[(size_t)row * OUT + j] = __float2half_rn((float)(wn - z) * sc);
    }
}

// ---------------------------------------------------------------------------
// Kernel C: fp16 WMMA GEMM  C[M][N] = Xh[M][K] * W[K][N]  (fp32 accumulate)
// Block tile 128x128x32, 8 warps (2x4), warp tile 64x32 (4x2 wmma frags).
// ---------------------------------------------------------------------------
#define BM 128
#define BN 128
#define BK 32

__global__ void __launch_bounds__(256, 1)
gemm_kernel(float* __restrict__ C, int M, int N, int K) {
    __shared__ __half As[BM][BK + 8];   // 128 x 40
    __shared__ __half Bs[BK][BN + 8];   // 32  x 136

    int tid  = threadIdx.x;
    int warp = tid >> 5;
    int wm   = warp & 1;     // 0..1 -> 64-row slab
    int wn   = warp >> 1;    // 0..3 -> 32-col slab

    int bm = blockIdx.y * BM;
    int bn = blockIdx.x * BN;

    wmma::fragment<wmma::accumulator, 16, 16, 16, float> acc[4][2];
#pragma unroll
    for (int i = 0; i < 4; i++)
#pragma unroll
        for (int j = 0; j < 2; j++)
            wmma::fill_fragment(acc[i][j], 0.0f);

    for (int k0 = 0; k0 < K; k0 += BK) {
        // Load A tile: 128x32 halves = 512 int4 chunks
#pragma unroll
        for (int c = 0; c < 2; c++) {
            int idx = tid + c * 256;
            int row = idx >> 2;            // / 4
            int col = (idx & 3) << 3;      // * 8
            const int4* src = reinterpret_cast<const int4*>(
                &g_X[(size_t)(bm + row) * K + k0 + col]);
            *reinterpret_cast<int4*>(&As[row][col]) = *src;
        }
        // Load B tile: 32x128 halves = 512 int4 chunks
#pragma unroll
        for (int c = 0; c < 2; c++) {
            int idx = tid + c * 256;
            int row = idx >> 4;            // / 16
            int col = (idx & 15) << 3;     // * 8
            const int4* src = reinterpret_cast<const int4*>(
                &g_W[(size_t)(k0 + row) * N + bn + col]);
            *reinterpret_cast<int4*>(&Bs[row][col]) = *src;
        }
        __syncthreads();

#pragma unroll
        for (int kk = 0; kk < BK; kk += 16) {
            wmma::fragment<wmma::matrix_a, 16, 16, 16, __half, wmma::row_major> af[4];
            wmma::fragment<wmma::matrix_b, 16, 16, 16, __half, wmma::row_major> bf[2];
#pragma unroll
            for (int i = 0; i < 4; i++)
                wmma::load_matrix_sync(af[i], &As[wm * 64 + i * 16][kk], BK + 8);
#pragma unroll
            for (int j = 0; j < 2; j++)
                wmma::load_matrix_sync(bf[j], &Bs[kk][wn * 32 + j * 16], BN + 8);
#pragma unroll
            for (int i = 0; i < 4; i++)
#pragma unroll
                for (int j = 0; j < 2; j++)
                    wmma::mma_sync(acc[i][j], af[i], bf[j], acc[i][j]);
        }
        __syncthreads();
    }

#pragma unroll
    for (int i = 0; i < 4; i++)
#pragma unroll
        for (int j = 0; j < 2; j++) {
            float* dst = &C[(size_t)(bm + wm * 64 + i * 16) * N + bn + wn * 32 + j * 16];
            wmma::store_matrix_sync(dst, acc[i][j], N, wmma::mem_row_major);
        }
}

// ---------------------------------------------------------------------------
// Launch
// ---------------------------------------------------------------------------
extern "C" void kernel_launch(void* const* d_in, const int* in_sizes, int n_in,
                              void* d_out, int out_size) {
    const float* x   = (const float*)d_in[0];
    const int*   qw  = (const int*)d_in[1];
    const int*   qz  = (const int*)d_in[2];
    const int*   qs  = (const int*)d_in[3];
    const float* qsz = (const float*)d_in[4];
    const float* qss = (const float*)d_in[5];
    const int*   gix = (const int*)d_in[6];

    int IN  = in_sizes[6];                       // 4096 (g_idx length)
    int OUT = (int)(((long long)in_sizes[1] * 8) / IN);  // 4096
    int M   = in_sizes[0] / IN;                  // 8192
    int K   = IN;
    int N   = OUT;

    float* out = (float*)d_out;

    // A: convert x to fp16
    {
        int n4 = (M * K) / 4;
        int threads = 256;
        int blocks = (n4 + threads - 1) / threads;
        convert_x_kernel<<<blocks, threads>>>(x, n4);
    }

    // B: dequantize weights
    {
        int total = (IN / 8) * OUT;
        int threads = 256;
        int blocks = (total + threads - 1) / threads;
        dequant_kernel<<<blocks, threads>>>(qw, qz, qs, qsz, qss, gix, IN, OUT);
    }

    // C: GEMM
    {
        dim3 grid(N / BN, M / BM);   // (32, 64)
        gemm_kernel<<<grid, 256>>>(out, M, N, K);
    }
}

// round 3
// speedup vs baseline: 2.4284x; 2.4284x over previous
#include <cuda_runtime.h>
#include <cuda_fp16.h>
#include <mma.h>
#include <cstdint>

using namespace nvcuda;

// Fixed problem shape: B=4, S=2048 -> M=8192, K=IN=4096, N=OUT=4096, group=32
#define IN_MAX  4096
#define OUT_MAX 4096
#define M_MAX   8192

// Static device scratch (allocation-free per harness rules)
__device__ __half g_X[(size_t)M_MAX * IN_MAX];     // x in fp16, [M][K]
__device__ __half g_WT[(size_t)OUT_MAX * IN_MAX];  // dequantized W^T, [N][K] K-major

// ============================================================================
// cp.async helpers (sm_80+, valid on plain sm_103 target)
// ============================================================================
__device__ __forceinline__ uint32_t smem_to_u32(const void* p) {
    uint32_t a;
    asm("{ .reg .u64 t; cvta.to.shared.u64 t, %1; cvt.u32.u64 %0, t; }" : "=r"(a) : "l"(p));
    return a;
}
__device__ __forceinline__ void cp_async16(uint32_t dst, const void* src) {
    asm volatile("cp.async.cg.shared.global [%0], [%1], 16;" :: "r"(dst), "l"(src));
}
__device__ __forceinline__ void cp_async_commit() {
    asm volatile("cp.async.commit_group;" ::: "memory");
}
template <int N>
__device__ __forceinline__ void cp_async_wait() {
    asm volatile("cp.async.wait_group %0;" :: "n"(N) : "memory");
}

// ============================================================================
// Kernel A: x fp32 -> fp16
// ============================================================================
__global__ void convert_x_kernel(const float* __restrict__ x, int n4) {
    int i = blockIdx.x * blockDim.x + threadIdx.x;
    if (i < n4) {
        float4 v = reinterpret_cast<const float4*>(x)[i];
        __half2 a = __floats2half2_rn(v.x, v.y);
        __half2 b = __floats2half2_rn(v.z, v.w);
        __half2* o = reinterpret_cast<__half2*>(g_X) + 2 * (size_t)i;
        o[0] = a;
        o[1] = b;
    }
}

// ============================================================================
// Kernel B: dequant 4-bit -> fp16, TRANSPOSED [N][K] (one 16B store/thread)
// ============================================================================
__global__ void dequant_kernel(const int* __restrict__ qweight,
                               const int* __restrict__ qzeros,
                               const int* __restrict__ qscales,
                               const float* __restrict__ qscales_zeros,
                               const float* __restrict__ qscales_scales,
                               const int* __restrict__ g_idx,
                               int K, int N) {
    int idx = blockIdx.x * blockDim.x + threadIdx.x;
    int P = K >> 3;
    if (idx >= P * N) return;
    int p = idx / N;
    int j = idx - p * N;

    // 8 consecutive K rows (p*8..p*8+7) lie in one group (group size 32, 8|32)
    int g = g_idx[p * 8];
    int z = (int)(((unsigned)qzeros[g * (N >> 3) + (j >> 3)] >> ((j & 7) * 4)) & 15u) + 1;
    float sc = ((float)qscales[(size_t)g * N + j] - qscales_zeros[g]) * qscales_scales[g];

    unsigned w = (unsigned)qweight[idx];
    __half h[8];
#pragma unroll
    for (int r = 0; r < 8; r++) {
        int wn = (int)((w >> (4 * r)) & 15u);
        h[r] = __float2half_rn((float)(wn - z) * sc);
    }
    *reinterpret_cast<int4*>(&g_WT[(size_t)j * K + p * 8]) = *reinterpret_cast<int4*>(h);
}

// ============================================================================
// Kernel C: pipelined WMMA GEMM
//   C[M][N] = g_X[M][K] * g_WT[N][K]^T,  fp16 in / fp32 accum
// CTA tile 128x256x32, 8 warps (2x4), warp tile 64x64 (4x4 frags),
// 3-stage cp.async pipeline, pad-8 smem (80B rows, conflict-free LDSM).
// ============================================================================
#define BM 128
#define BN 256
#define BK 32
#define STAGES 3
#define LDA (BK + 8)          // 40 halves = 80 bytes
#define LDB (BK + 8)

static constexpr int A_ST = BM * LDA * 2;          // 10240 B per stage
static constexpr int B_ST = BN * LDB * 2;          // 20480 B per stage
static constexpr int OFF_B = STAGES * A_ST;        // 30720
static constexpr int SMEM_DYN = OFF_B + STAGES * B_ST + 16;  // ~92KB

__device__ __forceinline__ void load_stage(char* dsm, uint32_t sbase, int stage,
                                           const __half* Abase, const __half* Bbase,
                                           int k0, int K, int tid, bool active) {
    if (active) {
        uint32_t aoff = sbase + stage * A_ST;
        uint32_t boff = sbase + OFF_B + stage * B_ST;
        // A: 128 rows x 4 chunks (16B each) = 512 chunks -> 2 per thread
#pragma unroll
        for (int c = 0; c < 2; c++) {
            int i = tid + c * 256;
            int row = i >> 2;
            int cc = i & 3;
            cp_async16(aoff + row * (LDA * 2) + cc * 16,
                       (const char*)(Abase + (size_t)row * K + k0) + cc * 16);
        }
        // B: 256 rows x 4 chunks = 1024 chunks -> 4 per thread
#pragma unroll
        for (int c = 0; c < 4; c++) {
            int i = tid + c * 256;
            int row = i >> 2;
            int cc = i & 3;
            cp_async16(boff + row * (LDB * 2) + cc * 16,
                       (const char*)(Bbase + (size_t)row * K + k0) + cc * 16);
        }
    }
    cp_async_commit();  // always commit (possibly-empty group keeps wait invariant)
}

__global__ void __launch_bounds__(256, 1)
gemm_kernel(float* __restrict__ C, int M, int N, int K) {
    extern __shared__ char dsm[];
    uint32_t sbase = smem_to_u32(dsm);

    int tid  = threadIdx.x;
    int warp = tid >> 5;
    int wm   = warp & 1;      // 0..1 -> 64-row slab
    int wn   = warp >> 1;     // 0..3 -> 64-col slab

    int bm = blockIdx.y * BM;
    int bn = blockIdx.x * BN;

    const __half* Abase = &g_X[(size_t)bm * K];
    const __half* Bbase = &g_WT[(size_t)bn * K];

    wmma::fragment<wmma::accumulator, 16, 16, 16, float> acc[4][4];
#pragma unroll
    for (int i = 0; i < 4; i++)
#pragma unroll
        for (int j = 0; j < 4; j++)
            wmma::fill_fragment(acc[i][j], 0.0f);

    int KT = K / BK;  // 128

    // Prologue: stages 0 and 1
    load_stage(dsm, sbase, 0, Abase, Bbase, 0, K, tid, true);
    load_stage(dsm, sbase, 1, Abase, Bbase, BK, K, tid, true);

    for (int kt = 0; kt < KT; kt++) {
        int st = kt % STAGES;
        cp_async_wait<1>();      // tile kt resident
        __syncthreads();         // also: all warps finished reading stage (kt-1)%3

        // Issue loads for tile kt+2 into stage (kt+2)%3 (the one freed last iter)
        load_stage(dsm, sbase, (kt + 2) % STAGES, Abase, Bbase,
                   (kt + 2) * BK, K, tid, (kt + 2) < KT);

        const __half* As = (const __half*)(dsm + st * A_ST);
        const __half* Bs = (const __half*)(dsm + OFF_B + st * B_ST);

#pragma unroll
        for (int kk = 0; kk < BK; kk += 16) {
            wmma::fragment<wmma::matrix_a, 16, 16, 16, __half, wmma::row_major> af[4];
            wmma::fragment<wmma::matrix_b, 16, 16, 16, __half, wmma::col_major> bf[4];
#pragma unroll
            for (int i = 0; i < 4; i++)
                wmma::load_matrix_sync(af[i], As + (size_t)(wm * 64 + i * 16) * LDA + kk, LDA);
#pragma unroll
            for (int j = 0; j < 4; j++)
                wmma::load_matrix_sync(bf[j], Bs + (size_t)(wn * 64 + j * 16) * LDB + kk, LDB);
#pragma unroll
            for (int i = 0; i < 4; i++)
#pragma unroll
                for (int j = 0; j < 4; j++)
                    wmma::mma_sync(acc[i][j], af[i], bf[j], acc[i][j]);
        }
    }

    // Epilogue: direct fp32 stores
#pragma unroll
    for (int i = 0; i < 4; i++)
#pragma unroll
        for (int j = 0; j < 4; j++) {
            float* dst = &C[(size_t)(bm + wm * 64 + i * 16) * N + bn + wn * 64 + j * 16];
            wmma::store_matrix_sync(dst, acc[i][j], N, wmma::mem_row_major);
        }
}

// ============================================================================
// Launch
// ============================================================================
extern "C" void kernel_launch(void* const* d_in, const int* in_sizes, int n_in,
                              void* d_out, int out_size) {
    const float* x   = (const float*)d_in[0];
    const int*   qw  = (const int*)d_in[1];
    const int*   qz  = (const int*)d_in[2];
    const int*   qs  = (const int*)d_in[3];
    const float* qsz = (const float*)d_in[4];
    const float* qss = (const float*)d_in[5];
    const int*   gix = (const int*)d_in[6];

    int K = in_sizes[6];                                  // IN = 4096
    int N = (int)(((long long)in_sizes[1] * 8) / K);      // OUT = 4096
    int M = in_sizes[0] / K;                              // 8192

    float* out = (float*)d_out;

    // A: fp32 -> fp16
    {
        int n4 = (M * K) / 4;
        convert_x_kernel<<<(n4 + 255) / 256, 256>>>(x, n4);
    }
    // B: dequant -> W^T fp16
    {
        int total = (K / 8) * N;
        dequant_kernel<<<(total + 255) / 256, 256>>>(qw, qz, qs, qsz, qss, gix, K, N);
    }
    // C: pipelined WMMA GEMM
    {
        cudaFuncSetAttribute(gemm_kernel,
                             cudaFuncAttributeMaxDynamicSharedMemorySize, SMEM_DYN);
        dim3 grid(N / BN, M / BM);   // (16, 64)
        gemm_kernel<<<grid, 256, SMEM_DYN>>>(out, M, N, K);
    }
}

// round 4
// speedup vs baseline: 2.6739x; 1.1011x over previous
#include <cuda_runtime.h>
#include <cuda_fp16.h>
#include <mma.h>
#include <cstdint>

using namespace nvcuda;

// Fixed problem shape: B=4, S=2048 -> M=8192, K=IN=4096, N=OUT=4096, group=32
#define IN_MAX  4096
#define OUT_MAX 4096
#define M_MAX   8192

// Static device scratch (allocation-free per harness rules)
__device__ __half g_X[(size_t)M_MAX * IN_MAX];     // x in fp16, [M][K]
__device__ __half g_WT[(size_t)OUT_MAX * IN_MAX];  // dequantized W^T, [N][K] K-major

// ============================================================================
// cp.async helpers (sm_80+, valid on plain sm_103 target)
// ============================================================================
__device__ __forceinline__ uint32_t smem_to_u32(const void* p) {
    uint32_t a;
    asm("{ .reg .u64 t; cvta.to.shared.u64 t, %1; cvt.u32.u64 %0, t; }" : "=r"(a) : "l"(p));
    return a;
}
__device__ __forceinline__ void cp_async16(uint32_t dst, const void* src) {
    asm volatile("cp.async.cg.shared.global [%0], [%1], 16;" :: "r"(dst), "l"(src));
}
__device__ __forceinline__ void cp_async_commit() {
    asm volatile("cp.async.commit_group;" ::: "memory");
}
template <int N>
__device__ __forceinline__ void cp_async_wait() {
    asm volatile("cp.async.wait_group %0;" :: "n"(N) : "memory");
}

// ============================================================================
// Kernel A: x fp32 -> fp16
// ============================================================================
__global__ void convert_x_kernel(const float* __restrict__ x, int n4) {
    int i = blockIdx.x * blockDim.x + threadIdx.x;
    if (i < n4) {
        float4 v = reinterpret_cast<const float4*>(x)[i];
        __half2 a = __floats2half2_rn(v.x, v.y);
        __half2 b = __floats2half2_rn(v.z, v.w);
        __half2* o = reinterpret_cast<__half2*>(g_X) + 2 * (size_t)i;
        o[0] = a;
        o[1] = b;
    }
}

// ============================================================================
// Kernel B: dequant 4-bit -> fp16, TRANSPOSED [N][K] (one 16B store/thread)
// ============================================================================
__global__ void dequant_kernel(const int* __restrict__ qweight,
                               const int* __restrict__ qzeros,
                               const int* __restrict__ qscales,
                               const float* __restrict__ qscales_zeros,
                               const float* __restrict__ qscales_scales,
                               const int* __restrict__ g_idx,
                               int K, int N) {
    int idx = blockIdx.x * blockDim.x + threadIdx.x;
    int P = K >> 3;
    if (idx >= P * N) return;
    int p = idx / N;
    int j = idx - p * N;

    // 8 consecutive K rows (p*8..p*8+7) lie in one group (group size 32, 8|32)
    int g = g_idx[p * 8];
    int z = (int)(((unsigned)qzeros[g * (N >> 3) + (j >> 3)] >> ((j & 7) * 4)) & 15u) + 1;
    float sc = ((float)qscales[(size_t)g * N + j] - qscales_zeros[g]) * qscales_scales[g];

    unsigned w = (unsigned)qweight[idx];
    __half h[8];
#pragma unroll
    for (int r = 0; r < 8; r++) {
        int wn = (int)((w >> (4 * r)) & 15u);
        h[r] = __float2half_rn((float)(wn - z) * sc);
    }
    *reinterpret_cast<int4*>(&g_WT[(size_t)j * K + p * 8]) = *reinterpret_cast<int4*>(h);
}

// ============================================================================
// Kernel C: pipelined WMMA GEMM
//   C[M][N] = g_X[M][K] * g_WT[N][K]^T,  fp16 in / fp32 accum
// CTA tile 128x256x64, 8 warps (2x4), warp tile 64x64 (4x4 frags),
// 3-stage cp.async pipeline (166KB smem), pad-8 smem rows (144B stride,
// conflict-free 8-row LDSM phases: banks {0,4,8,...,28}).
// ============================================================================
#define BM 128
#define BN 256
#define BK 64
#define STAGES 3
#define LDA (BK + 8)          // 72 halves = 144 bytes
#define LDB (BK + 8)

static constexpr int A_ST = BM * LDA * 2;          // 18432 B per stage
static constexpr int B_ST = BN * LDB * 2;          // 36864 B per stage
static constexpr int OFF_B = STAGES * A_ST;        // 55296
static constexpr int SMEM_DYN = OFF_B + STAGES * B_ST + 16;  // ~166KB

__device__ __forceinline__ void load_stage(uint32_t sbase, int stage,
                                           const __half* Abase, const __half* Bbase,
                                           int k0, int K, int tid, bool active) {
    if (active) {
        uint32_t aoff = sbase + stage * A_ST;
        uint32_t boff = sbase + OFF_B + stage * B_ST;
        // A: 128 rows x 8 chunks (16B each) = 1024 chunks -> 4 per thread
#pragma unroll
        for (int c = 0; c < 4; c++) {
            int i = tid + c * 256;
            int row = i >> 3;
            int cc = i & 7;
            cp_async16(aoff + row * (LDA * 2) + cc * 16,
                       (const char*)(Abase + (size_t)row * K + k0) + cc * 16);
        }
        // B: 256 rows x 8 chunks = 2048 chunks -> 8 per thread
#pragma unroll
        for (int c = 0; c < 8; c++) {
            int i = tid + c * 256;
            int row = i >> 3;
            int cc = i & 7;
            cp_async16(boff + row * (LDB * 2) + cc * 16,
                       (const char*)(Bbase + (size_t)row * K + k0) + cc * 16);
        }
    }
    cp_async_commit();  // always commit (possibly-empty group keeps wait invariant)
}

__global__ void __launch_bounds__(256, 1)
gemm_kernel(float* __restrict__ C, int M, int N, int K) {
    extern __shared__ char dsm[];
    uint32_t sbase = smem_to_u32(dsm);

    int tid  = threadIdx.x;
    int warp = tid >> 5;
    int wm   = warp & 1;      // 0..1 -> 64-row slab
    int wn   = warp >> 1;     // 0..3 -> 64-col slab

    int bm = blockIdx.y * BM;
    int bn = blockIdx.x * BN;

    const __half* Abase = &g_X[(size_t)bm * K];
    const __half* Bbase = &g_WT[(size_t)bn * K];

    wmma::fragment<wmma::accumulator, 16, 16, 16, float> acc[4][4];
#pragma unroll
    for (int i = 0; i < 4; i++)
#pragma unroll
        for (int j = 0; j < 4; j++)
            wmma::fill_fragment(acc[i][j], 0.0f);

    int KT = K / BK;  // 64

    // Prologue: stages 0 and 1
    load_stage(sbase, 0, Abase, Bbase, 0, K, tid, true);
    load_stage(sbase, 1, Abase, Bbase, BK, K, tid, true);

    for (int kt = 0; kt < KT; kt++) {
        int st = kt % STAGES;
        cp_async_wait<1>();      // tile kt resident
        __syncthreads();         // all warps done reading stage (kt-1)%3

        // Issue loads for tile kt+2 into the stage freed last iteration
        load_stage(sbase, (kt + 2) % STAGES, Abase, Bbase,
                   (kt + 2) * BK, K, tid, (kt + 2) < KT);

        const __half* As = (const __half*)(dsm + st * A_ST);
        const __half* Bs = (const __half*)(dsm + OFF_B + st * B_ST);

#pragma unroll
        for (int kk = 0; kk < BK; kk += 16) {
            wmma::fragment<wmma::matrix_a, 16, 16, 16, __half, wmma::row_major> af[4];
            wmma::fragment<wmma::matrix_b, 16, 16, 16, __half, wmma::col_major> bf[4];
#pragma unroll
            for (int i = 0; i < 4; i++)
                wmma::load_matrix_sync(af[i], As + (size_t)(wm * 64 + i * 16) * LDA + kk, LDA);
#pragma unroll
            for (int j = 0; j < 4; j++)
                wmma::load_matrix_sync(bf[j], Bs + (size_t)(wn * 64 + j * 16) * LDB + kk, LDB);
#pragma unroll
            for (int i = 0; i < 4; i++)
#pragma unroll
                for (int j = 0; j < 4; j++)
                    wmma::mma_sync(acc[i][j], af[i], bf[j], acc[i][j]);
        }
    }

    // Epilogue: direct fp32 stores
#pragma unroll
    for (int i = 0; i < 4; i++)
#pragma unroll
        for (int j = 0; j < 4; j++) {
            float* dst = &C[(size_t)(bm + wm * 64 + i * 16) * N + bn + wn * 64 + j * 16];
            wmma::store_matrix_sync(dst, acc[i][j], N, wmma::mem_row_major);
        }
}

// ============================================================================
// Launch
// ============================================================================
extern "C" void kernel_launch(void* const* d_in, const int* in_sizes, int n_in,
                              void* d_out, int out_size) {
    const float* x   = (const float*)d_in[0];
    const int*   qw  = (const int*)d_in[1];
    const int*   qz  = (const int*)d_in[2];
    const int*   qs  = (const int*)d_in[3];
    const float* qsz = (const float*)d_in[4];
    const float* qss = (const float*)d_in[5];
    const int*   gix = (const int*)d_in[6];

    int K = in_sizes[6];                                  // IN = 4096
    int N = (int)(((long long)in_sizes[1] * 8) / K);      // OUT = 4096
    int M = in_sizes[0] / K;                              // 8192

    float* out = (float*)d_out;

    // A: fp32 -> fp16
    {
        int n4 = (M * K) / 4;
        convert_x_kernel<<<(n4 + 255) / 256, 256>>>(x, n4);
    }
    // B: dequant -> W^T fp16
    {
        int total = (K / 8) * N;
        dequant_kernel<<<(total + 255) / 256, 256>>>(qw, qz, qs, qsz, qss, gix, K, N);
    }
    // C: pipelined WMMA GEMM
    {
        cudaFuncSetAttribute(gemm_kernel,
                             cudaFuncAttributeMaxDynamicSharedMemorySize, SMEM_DYN);
        dim3 grid(N / BN, M / BM);   // (16, 64)
        gemm_kernel<<<grid, 256, SMEM_DYN>>>(out, M, N, K);
    }
}

// round 5
// speedup vs baseline: 2.6887x; 1.0055x over previous
#include <cuda_runtime.h>
#include <cuda_fp16.h>
#include <mma.h>
#include <cstdint>

using namespace nvcuda;

// Fixed problem shape: B=4, S=2048 -> M=8192, K=IN=4096, N=OUT=4096, group=32
#define IN_MAX  4096
#define OUT_MAX 4096
#define M_MAX   8192

// Static device scratch (allocation-free per harness rules)
__device__ __half g_X[(size_t)M_MAX * IN_MAX];     // x in fp16, [M][K]
__device__ __half g_WT[(size_t)OUT_MAX * IN_MAX];  // dequantized W^T, [N][K] K-major

// ============================================================================
// cp.async helpers (sm_80+, valid on plain sm_103 target)
// ============================================================================
__device__ __forceinline__ uint32_t smem_to_u32(const void* p) {
    uint32_t a;
    asm("{ .reg .u64 t; cvta.to.shared.u64 t, %1; cvt.u32.u64 %0, t; }" : "=r"(a) : "l"(p));
    return a;
}
__device__ __forceinline__ void cp_async16(uint32_t dst, const void* src) {
    asm volatile("cp.async.cg.shared.global [%0], [%1], 16;" :: "r"(dst), "l"(src));
}
__device__ __forceinline__ void cp_async_commit() {
    asm volatile("cp.async.commit_group;" ::: "memory");
}
template <int N>
__device__ __forceinline__ void cp_async_wait() {
    asm volatile("cp.async.wait_group %0;" :: "n"(N) : "memory");
}

// ============================================================================
// Kernel A: x fp32 -> fp16
// ============================================================================
__global__ void convert_x_kernel(const float* __restrict__ x, int n4) {
    int i = blockIdx.x * blockDim.x + threadIdx.x;
    if (i < n4) {
        float4 v = reinterpret_cast<const float4*>(x)[i];
        __half2 a = __floats2half2_rn(v.x, v.y);
        __half2 b = __floats2half2_rn(v.z, v.w);
        __half2* o = reinterpret_cast<__half2*>(g_X) + 2 * (size_t)i;
        o[0] = a;
        o[1] = b;
    }
}

// ============================================================================
// Kernel B: dequant 4-bit -> fp16, TRANSPOSED [N][K] (one 16B store/thread)
// ============================================================================
__global__ void dequant_kernel(const int* __restrict__ qweight,
                               const int* __restrict__ qzeros,
                               const int* __restrict__ qscales,
                               const float* __restrict__ qscales_zeros,
                               const float* __restrict__ qscales_scales,
                               const int* __restrict__ g_idx,
                               int K, int N) {
    int idx = blockIdx.x * blockDim.x + threadIdx.x;
    int P = K >> 3;
    if (idx >= P * N) return;
    int p = idx / N;
    int j = idx - p * N;

    // 8 consecutive K rows (p*8..p*8+7) lie in one group (group size 32, 8|32)
    int g = g_idx[p * 8];
    int z = (int)(((unsigned)qzeros[g * (N >> 3) + (j >> 3)] >> ((j & 7) * 4)) & 15u) + 1;
    float sc = ((float)qscales[(size_t)g * N + j] - qscales_zeros[g]) * qscales_scales[g];

    unsigned w = (unsigned)qweight[idx];
    __half h[8];
#pragma unroll
    for (int r = 0; r < 8; r++) {
        int wn = (int)((w >> (4 * r)) & 15u);
        h[r] = __float2half_rn((float)(wn - z) * sc);
    }
    *reinterpret_cast<int4*>(&g_WT[(size_t)j * K + p * 8]) = *reinterpret_cast<int4*>(h);
}

// ============================================================================
// Kernel C: pipelined WMMA GEMM with register double-buffering
//   C[M][N] = g_X[M][K] * g_WT[N][K]^T,  fp16 in / fp32 accum
// CTA tile 128x256x64, 8 warps (2x4), warp tile 64x64 (4x4 frags),
// 4-stage cp.async pipeline (221KB smem), pad-8 smem rows (144B stride,
// conflict-free 8-row LDSM phases), ping-pong fragment prefetch.
// ============================================================================
#define BM 128
#define BN 256
#define BK 64
#define STAGES 4
#define LDA (BK + 8)          // 72 halves = 144 bytes
#define LDB (BK + 8)

static constexpr int A_ST = BM * LDA * 2;          // 18432 B per stage
static constexpr int B_ST = BN * LDB * 2;          // 36864 B per stage
static constexpr int OFF_B = STAGES * A_ST;        // 73728
static constexpr int SMEM_DYN = OFF_B + STAGES * B_ST + 16;  // ~221KB

__device__ __forceinline__ void load_stage(uint32_t sbase, int stage,
                                           const __half* Abase, const __half* Bbase,
                                           int k0, int K, int tid, bool active) {
    if (active) {
        uint32_t aoff = sbase + stage * A_ST;
        uint32_t boff = sbase + OFF_B + stage * B_ST;
        // A: 128 rows x 8 chunks (16B each) = 1024 chunks -> 4 per thread
#pragma unroll
        for (int c = 0; c < 4; c++) {
            int i = tid + c * 256;
            int row = i >> 3;
            int cc = i & 7;
            cp_async16(aoff + row * (LDA * 2) + cc * 16,
                       (const char*)(Abase + (size_t)row * K + k0) + cc * 16);
        }
        // B: 256 rows x 8 chunks = 2048 chunks -> 8 per thread
#pragma unroll
        for (int c = 0; c < 8; c++) {
            int i = tid + c * 256;
            int row = i >> 3;
            int cc = i & 7;
            cp_async16(boff + row * (LDB * 2) + cc * 16,
                       (const char*)(Bbase + (size_t)row * K + k0) + cc * 16);
        }
    }
    cp_async_commit();  // always commit (possibly-empty group keeps wait invariant)
}

typedef wmma::fragment<wmma::matrix_a, 16, 16, 16, __half, wmma::row_major> FragA;
typedef wmma::fragment<wmma::matrix_b, 16, 16, 16, __half, wmma::col_major> FragB;
typedef wmma::fragment<wmma::accumulator, 16, 16, 16, float> FragC;

__device__ __forceinline__ void load_frags(FragA af[4], FragB bf[4],
                                           const __half* As, const __half* Bs,
                                           int wm, int wn, int kk) {
#pragma unroll
    for (int i = 0; i < 4; i++)
        wmma::load_matrix_sync(af[i], As + (size_t)(wm * 64 + i * 16) * LDA + kk, LDA);
#pragma unroll
    for (int j = 0; j < 4; j++)
        wmma::load_matrix_sync(bf[j], Bs + (size_t)(wn * 64 + j * 16) * LDB + kk, LDB);
}

__global__ void __launch_bounds__(256, 1)
gemm_kernel(float* __restrict__ C, int M, int N, int K) {
    extern __shared__ char dsm[];
    uint32_t sbase = smem_to_u32(dsm);

    int tid  = threadIdx.x;
    int warp = tid >> 5;
    int wm   = warp & 1;      // 0..1 -> 64-row slab
    int wn   = warp >> 1;     // 0..3 -> 64-col slab

    int bm = blockIdx.y * BM;
    int bn = blockIdx.x * BN;

    const __half* Abase = &g_X[(size_t)bm * K];
    const __half* Bbase = &g_WT[(size_t)bn * K];

    FragC acc[4][4];
#pragma unroll
    for (int i = 0; i < 4; i++)
#pragma unroll
        for (int j = 0; j < 4; j++)
            wmma::fill_fragment(acc[i][j], 0.0f);

    int KT = K / BK;  // 64

    // Prologue: fill STAGES-1 stages
#pragma unroll
    for (int s = 0; s < STAGES - 1; s++)
        load_stage(sbase, s, Abase, Bbase, s * BK, K, tid, true);

    FragA af[2][4];
    FragB bf[2][4];

    for (int kt = 0; kt < KT; kt++) {
        int st = kt % STAGES;
        cp_async_wait<STAGES - 2>();   // tile kt resident
        __syncthreads();               // all warps done reading stage (kt-1)%STAGES

        // Issue loads for tile kt+STAGES-1 into the stage freed last iteration
        load_stage(sbase, (kt + STAGES - 1) % STAGES, Abase, Bbase,
                   (kt + STAGES - 1) * BK, K, tid, (kt + STAGES - 1) < KT);

        const __half* As = (const __half*)(dsm + st * A_ST);
        const __half* Bs = (const __half*)(dsm + OFF_B + st * B_ST);

        // Ping-pong fragment pipeline over the 4 k16 steps of this chunk
        load_frags(af[0], bf[0], As, Bs, wm, wn, 0);
#pragma unroll
        for (int kk = 0; kk < BK / 16; kk++) {
            int cur = kk & 1;
            if (kk < BK / 16 - 1)
                load_frags(af[cur ^ 1], bf[cur ^ 1], As, Bs, wm, wn, (kk + 1) * 16);
#pragma unroll
            for (int i = 0; i < 4; i++)
#pragma unroll
                for (int j = 0; j < 4; j++)
                    wmma::mma_sync(acc[i][j], af[cur][i], bf[cur][j], acc[i][j]);
        }
    }

    // Epilogue: direct fp32 stores
#pragma unroll
    for (int i = 0; i < 4; i++)
#pragma unroll
        for (int j = 0; j < 4; j++) {
            float* dst = &C[(size_t)(bm + wm * 64 + i * 16) * N + bn + wn * 64 + j * 16];
            wmma::store_matrix_sync(dst, acc[i][j], N, wmma::mem_row_major);
        }
}

// ============================================================================
// Launch
// ============================================================================
extern "C" void kernel_launch(void* const* d_in, const int* in_sizes, int n_in,
                              void* d_out, int out_size) {
    const float* x   = (const float*)d_in[0];
    const int*   qw  = (const int*)d_in[1];
    const int*   qz  = (const int*)d_in[2];
    const int*   qs  = (const int*)d_in[3];
    const float* qsz = (const float*)d_in[4];
    const float* qss = (const float*)d_in[5];
    const int*   gix = (const int*)d_in[6];

    int K = in_sizes[6];                                  // IN = 4096
    int N = (int)(((long long)in_sizes[1] * 8) / K);      // OUT = 4096
    int M = in_sizes[0] / K;                              // 8192

    float* out = (float*)d_out;

    // A: fp32 -> fp16
    {
        int n4 = (M * K) / 4;
        convert_x_kernel<<<(n4 + 255) / 256, 256>>>(x, n4);
    }
    // B: dequant -> W^T fp16
    {
        int total = (K / 8) * N;
        dequant_kernel<<<(total + 255) / 256, 256>>>(qw, qz, qs, qsz, qss, gix, K, N);
    }
    // C: pipelined WMMA GEMM
    {
        cudaFuncSetAttribute(gemm_kernel,
                             cudaFuncAttributeMaxDynamicSharedMemorySize, SMEM_DYN);
        dim3 grid(N / BN, M / BM);   // (16, 64)
        gemm_kernel<<<grid, 256, SMEM_DYN>>>(out, M, N, K);
    }
}